// round 9
// baseline (speedup 1.0000x reference)
#include <cuda_runtime.h>

#define W_IMG 3840
#define H_IMG 2160
#define TILE_W 30            // output columns per warp (lanes 1..30)
#define NW_X 128             // 3840 / 30
#define NW_Y 55              // vertical strips (40 or 39 rows)
#define WPB 8
#define NTHREADS 256
#define NBLOCKS ((NW_X * NW_Y) / WPB)   // 7040/8 = 880 blocks -> one wave at 6/SM

__device__ double g_num;
__device__ unsigned int g_cnt;
__device__ unsigned int g_ticket;

__constant__ float c_l[27];
__constant__ float c_Kc[9];

__launch_bounds__(NTHREADS, 6)
__global__ void shading_loss_kernel(const float* __restrict__ depth,
                                    const float* __restrict__ rgb,
                                    const int*   __restrict__ mask,
                                    float* __restrict__ out)
{
    const int tid  = threadIdx.x;
    const int lane = tid & 31;
    const int w    = tid >> 5;
    const int wid  = blockIdx.x * WPB + w;
    const int tx   = wid % NW_X;
    const int ty   = wid / NW_X;
    // 2160 = 15*40 + 40*39 : first 15 strips are 40 rows tall
    const int r0   = ty * 39 + min(ty, 15);
    const int hgt  = 39 + (ty < 15 ? 1 : 0);
    const int c0   = tx * TILE_W;
    const int col  = c0 - 1 + lane;
    const bool colin  = (col >= 0) && (col < W_IMG);
    const bool colrin = (col + 1 < W_IMG);
    const bool safe   = (tx >= 1) && (tx <= NW_X - 2) && (ty >= 1) && (ty <= NW_Y - 2);

    // camera inverse (adjugate) from constant bank — uniform arithmetic
    float a = c_Kc[0], b = c_Kc[1], cc = c_Kc[2];
    float d = c_Kc[3], e = c_Kc[4], f  = c_Kc[5];
    float g = c_Kc[6], h = c_Kc[7], i  = c_Kc[8];
    float A =  (e*i - f*h), B = -(d*i - f*g), C =  (d*h - e*g);
    float inv = 1.0f / (a*A + b*B + cc*C);
    const float K0 = A*inv,  K1 = -(b*i - cc*h)*inv,  K2 =  (b*f - cc*e)*inv;
    const float K3 = B*inv,  K4 =  (a*i - cc*g)*inv,  K5 = -(a*f - cc*d)*inv;
    const float K6 = C*inv,  K7 = -(a*h - b*g)*inv,   K8 =  (a*e - b*d)*inv;

    const float x = (float)col;
    float rx = K0 * x + K1 * (float)(r0 - 1) + K2;
    float ry = K3 * x + K4 * (float)(r0 - 1) + K5;
    float rz = K6 * x + K7 * (float)(r0 - 1) + K8;

    float acc = 0.0f;
    unsigned int cnt = 0;
    const bool emitlane = (lane >= 1) && (lane <= 30);
    const float inv9 = 1.0f / 9.0f;
    const int rend = r0 + hgt;

    float hsA0,hsA1,hsA2, hsB0,hsB1,hsB2;
    float qC0,qC1,qC2;
    int   mC;

#define ROW_SAFE                                                              \
    float dB = depth[off + W_IMG];                                           \
    float dR = depth[off + 1];                                               \
    int   m  = mask[off] > 0;                                                \
    int ro3 = off * 3;                                                       \
    float rg0 = rgb[ro3], rg1 = rgb[ro3 + 1], rg2 = rgb[ro3 + 2];            \
    SHADE_BODY

#define ROW_GEN                                                               \
    const bool rin  = ((unsigned)r < (unsigned)H_IMG);                       \
    const bool rnin = ((unsigned)(r + 1) < (unsigned)H_IMG);                 \
    float dB = (rnin && colin)  ? depth[off + W_IMG] : 0.0f;                 \
    float dR = (rin  && colrin) ? depth[off + 1]     : 0.0f;                 \
    int   m  = 0;                                                            \
    float rg0 = 0.0f, rg1 = 0.0f, rg2 = 0.0f;                                \
    if (rin && colin) {                                                      \
        m = mask[off] > 0;                                                   \
        int ro3 = off * 3;                                                   \
        rg0 = rgb[ro3]; rg1 = rgb[ro3 + 1]; rg2 = rgb[ro3 + 2];              \
    }                                                                        \
    SHADE_BODY

#define SHADE_BODY                                                            \
    float b0 = 0.0f, b1 = 0.0f, b2 = 0.0f;                                   \
    if (m) {                                                                 \
        float px = rx * dA, py = ry * dA, pz = rz * dA;                      \
        float axv = (rx + K0) * dR - px, ayv = (ry + K3) * dR - py, azv = (rz + K6) * dR - pz; \
        float bxv = (rx + K1) * dB - px, byv = (ry + K4) * dB - py, bzv = (rz + K7) * dB - pz; \
        float nx = ayv * bzv - azv * byv;                                    \
        float ny = azv * bxv - axv * bzv;                                    \
        float nz = axv * byv - ayv * bxv;                                    \
        float nn = nx*nx + ny*ny + nz*nz;                                    \
        float invn = rsqrtf(fmaxf(nn, 1e-24f));                              \
        nx *= invn; ny *= invn; nz *= invn;                                  \
        float nx2 = nx*nx, ny2 = ny*ny, nz2 = nz*nz;                         \
        float H1 = ny, H2 = nz, H3 = nx;                                     \
        float H4 = nx*ny, H5 = ny*nz;                                        \
        float H6 = 2.0f*nz2 - nx2 - ny2;                                     \
        float H7 = nz*nx, H8 = nx2 - ny2;                                    \
        b0 = c_l[0] + H1*c_l[3]  + H2*c_l[6]  + H3*c_l[9]  + H4*c_l[12] + H5*c_l[15] + H6*c_l[18] + H7*c_l[21] + H8*c_l[24]; \
        b1 = c_l[1] + H1*c_l[4]  + H2*c_l[7]  + H3*c_l[10] + H4*c_l[13] + H5*c_l[16] + H6*c_l[19] + H7*c_l[22] + H8*c_l[25]; \
        b2 = c_l[2] + H1*c_l[5]  + H2*c_l[8]  + H3*c_l[11] + H4*c_l[14] + H5*c_l[17] + H6*c_l[20] + H7*c_l[23] + H8*c_l[26]; \
    }                                                                        \
    float q0 = b0 - rg0, q1 = b1 - rg1, q2 = b2 - rg2;                       \
    float hs0, hs1, hs2;                                                     \
    {                                                                        \
        float ql0 = __shfl_up_sync(0xffffffffu, q0, 1), qr0 = __shfl_down_sync(0xffffffffu, q0, 1); \
        float ql1 = __shfl_up_sync(0xffffffffu, q1, 1), qr1 = __shfl_down_sync(0xffffffffu, q1, 1); \
        float ql2 = __shfl_up_sync(0xffffffffu, q2, 1), qr2 = __shfl_down_sync(0xffffffffu, q2, 1); \
        hs0 = ql0 + q0 + qr0;                                                \
        hs1 = ql1 + q1 + qr1;                                                \
        hs2 = ql2 + q2 + qr2;                                                \
    }                                                                        \
    dA = dB;                                                                 \
    off += W_IMG;                                                            \
    rx += K1; ry += K4; rz += K7;

#define EMIT                                                                  \
    if (emitlane && mC) {                                                    \
        float d0 = qC0 - (hsA0 + hsB0 + hs0) * inv9;                         \
        float d1 = qC1 - (hsA1 + hsB1 + hs1) * inv9;                         \
        float d2 = qC2 - (hsA2 + hsB2 + hs2) * inv9;                         \
        acc += d0*d0 + d1*d1 + d2*d2;                                        \
        cnt += 1u;                                                           \
    }

#define ROTATE                                                                \
    hsA0 = hsB0; hsA1 = hsB1; hsA2 = hsB2;                                   \
    hsB0 = hs0;  hsB1 = hs1;  hsB2 = hs2;                                    \
    qC0 = q0; qC1 = q1; qC2 = q2; mC = m;

    if (safe) {
        int off = (r0 - 1) * W_IMG + col;
        float dA = depth[off];
        { ROW_SAFE; hsA0 = hs0; hsA1 = hs1; hsA2 = hs2; (void)m; }
        { ROW_SAFE; hsB0 = hs0; hsB1 = hs1; hsB2 = hs2;
          qC0 = q0; qC1 = q1; qC2 = q2; mC = m; }
        #pragma unroll 2
        for (int r = r0 + 1; r <= rend; ++r) {
            ROW_SAFE;
            EMIT;
            ROTATE;
        }
    } else {
        int off = (r0 - 1) * W_IMG + col;
        float dA = 0.0f;
        if (colin && r0 >= 1) dA = depth[off];
        { int r = r0 - 1; ROW_GEN; hsA0 = hs0; hsA1 = hs1; hsA2 = hs2; (void)m; }
        { int r = r0;     ROW_GEN; hsB0 = hs0; hsB1 = hs1; hsB2 = hs2;
          qC0 = q0; qC1 = q1; qC2 = q2; mC = m; }
        #pragma unroll 1
        for (int r = r0 + 1; r <= rend; ++r) {
            ROW_GEN;
            EMIT;
            ROTATE;
        }
    }

    // ---- reduction: warp -> block -> global ----
    #pragma unroll
    for (int o = 16; o > 0; o >>= 1) {
        acc += __shfl_down_sync(0xffffffffu, acc, o);
        cnt += __shfl_down_sync(0xffffffffu, cnt, o);
    }
    __shared__ float s_red[WPB];
    __shared__ unsigned int s_redc[WPB];
    if (lane == 0) { s_red[w] = acc; s_redc[w] = cnt; }
    __syncthreads();
    if (tid == 0) {
        float aa = 0.0f; unsigned int cn = 0;
        #pragma unroll
        for (int k = 0; k < WPB; k++) { aa += s_red[k]; cn += s_redc[k]; }
        atomicAdd(&g_num, (double)aa);
        atomicAdd(&g_cnt, cn);
        __threadfence();
        unsigned int t = atomicAdd(&g_ticket, 1u);
        if (t == NBLOCKS - 1) {
            __threadfence();
            double num = g_num;
            unsigned int c2 = g_cnt;
            out[0] = (float)(num / ((double)c2 * 3.0));
            g_num = 0.0;
            g_cnt = 0u;
            g_ticket = 0u;
        }
    }
}

extern "C" void kernel_launch(void* const* d_in, const int* in_sizes, int n_in,
                              void* d_out, int out_size) {
    const float* depth = (const float*)d_in[0];
    const float* rgb   = (const float*)d_in[1];
    const int*   mask  = (const int*)d_in[2];
    const float* l     = (const float*)d_in[3];
    const float* Kc    = (const float*)d_in[4];

    // Stage uniform coefficients into the constant bank (graph-capturable D2D copies)
    cudaMemcpyToSymbolAsync(c_l,  l,  27 * sizeof(float), 0, cudaMemcpyDeviceToDevice);
    cudaMemcpyToSymbolAsync(c_Kc, Kc,  9 * sizeof(float), 0, cudaMemcpyDeviceToDevice);

    shading_loss_kernel<<<NBLOCKS, NTHREADS>>>(depth, rgb, mask, (float*)d_out);
}